// round 1
// baseline (speedup 1.0000x reference)
#include <cuda_runtime.h>
#include <cuda_bf16.h>
#include <cstdint>

// Problem constants
#define NMAT 512          // H = W = 512
#define NBATCH 96         // 32 * 3 images
#define BM 128
#define BN 128
#define BK 16
#define TM 8
#define TN 8
// threads per block = (BM/TM)*(BN/TN) = 16*16 = 256

// Scratch in device globals (no allocation allowed)
__device__ float g_T[NMAT * NMAT];     // T[k][n] = c_k * cos(pi*k*(2n+1)/(2N))
__device__ float g_Tt[NMAT * NMAT];    // transpose of T
__device__ float g_tmp[NBATCH * NMAT * NMAT]; // intermediate Y

// ---------------------------------------------------------------------------
// Build the orthonormal IDCT-III basis matrix.
// x[n] = sum_k c_k * X[k] * cos(pi*k*(2n+1)/(2N)), c_0=sqrt(1/N), c_k=sqrt(2/N)
// Argument k*(2n+1) <= 511*1023 = 522753 < 2^24 -> exact in fp32;
// divide by 1024 (power of two) is exact; cospif does precise pi-reduction.
// ---------------------------------------------------------------------------
__global__ void build_T_kernel(float* __restrict__ T, float* __restrict__ Tt) {
    int k = blockIdx.x;      // 0..511
    int n = threadIdx.x;     // 0..511
    float ck = (k == 0) ? rsqrtf((float)NMAT) : sqrtf(2.0f / (float)NMAT);
    float arg = (float)(k * (2 * n + 1)) * (1.0f / (2.0f * (float)NMAT));
    float val = ck * cospif(arg);
    T[k * NMAT + n]  = val;
    Tt[n * NMAT + k] = val;
}

// ---------------------------------------------------------------------------
// Batched SGEMM: C_z = A_z @ B_z, all matrices 512x512 row-major.
// strideA / strideB select batched vs broadcast operands (0 = broadcast).
// 128x128 block tile, BK=16, 8x8 register micro-tile per thread.
// ---------------------------------------------------------------------------
__global__ __launch_bounds__(256, 2)
void sgemm_batched(const float* __restrict__ Abase,
                   const float* __restrict__ Bbase,
                   float* __restrict__ Cbase,
                   long strideA, long strideB) {
    const float* A = Abase + (long)blockIdx.z * strideA;
    const float* B = Bbase + (long)blockIdx.z * strideB;
    float* Cp      = Cbase + (long)blockIdx.z * (long)(NMAT * NMAT);

    // +4 padding on As rows: store pattern As[c][row] becomes conflict-free
    __shared__ float As[BK][BM + 4];   // stored K-major: As[k][m]
    __shared__ float Bs[BK][BN];

    const int tid = threadIdx.x;
    const int tx = tid % 16;           // N-dir thread coord
    const int ty = tid / 16;           // M-dir thread coord

    const int rowBase = blockIdx.y * BM;
    const int colBase = blockIdx.x * BN;

    // A tile load: 128 rows x 16 cols, float4 along K. 512 float4 / 256 thr = 2 each.
    const int aRow  = tid / 4;          // 0..63
    const int aCol4 = (tid % 4) * 4;    // 0,4,8,12
    // B tile load: 16 rows x 128 cols, float4 along N. 512 float4 / 256 thr = 2 each.
    const int bRow  = tid / 32;         // 0..7
    const int bCol4 = (tid % 32) * 4;   // 0..124

    float acc[TM][TN] = {};

    for (int k0 = 0; k0 < NMAT; k0 += BK) {
        #pragma unroll
        for (int r = 0; r < 2; r++) {
            int row = aRow + r * 64;
            float4 v = *reinterpret_cast<const float4*>(
                &A[(long)(rowBase + row) * NMAT + k0 + aCol4]);
            As[aCol4 + 0][row] = v.x;
            As[aCol4 + 1][row] = v.y;
            As[aCol4 + 2][row] = v.z;
            As[aCol4 + 3][row] = v.w;
        }
        #pragma unroll
        for (int r = 0; r < 2; r++) {
            int row = bRow + r * 8;
            float4 v = *reinterpret_cast<const float4*>(
                &B[(long)(k0 + row) * NMAT + colBase + bCol4]);
            *reinterpret_cast<float4*>(&Bs[row][bCol4]) = v;
        }
        __syncthreads();

        #pragma unroll
        for (int kk = 0; kk < BK; kk++) {
            float ra[TM], rb[TN];
            #pragma unroll
            for (int i = 0; i < TM; i++) ra[i] = As[kk][ty * TM + i];
            #pragma unroll
            for (int j = 0; j < TN; j++) rb[j] = Bs[kk][tx * TN + j];
            #pragma unroll
            for (int i = 0; i < TM; i++)
                #pragma unroll
                for (int j = 0; j < TN; j++)
                    acc[i][j] = fmaf(ra[i], rb[j], acc[i][j]);
        }
        __syncthreads();
    }

    #pragma unroll
    for (int i = 0; i < TM; i++) {
        long row = rowBase + ty * TM + i;
        #pragma unroll
        for (int j = 0; j < TN; j += 4) {
            float4 v = make_float4(acc[i][j], acc[i][j + 1],
                                   acc[i][j + 2], acc[i][j + 3]);
            *reinterpret_cast<float4*>(
                &Cp[row * NMAT + colBase + tx * TN + j]) = v;
        }
    }
}

// ---------------------------------------------------------------------------
// kernel_launch: build basis, then two batched GEMM stages.
//   Stage 1: Y_img  = X_img @ T        (IDCT over width)
//   Stage 2: Out_img = T^T @ Y_img     (IDCT over height)
// ---------------------------------------------------------------------------
extern "C" void kernel_launch(void* const* d_in, const int* in_sizes, int n_in,
                              void* d_out, int out_size) {
    const float* X = (const float*)d_in[0];
    float* out = (float*)d_out;

    float *pT, *pTt, *pTmp;
    cudaGetSymbolAddress((void**)&pT,  g_T);
    cudaGetSymbolAddress((void**)&pTt, g_Tt);
    cudaGetSymbolAddress((void**)&pTmp, g_tmp);

    build_T_kernel<<<NMAT, NMAT>>>(pT, pTt);

    dim3 grid(NMAT / BN, NMAT / BM, NBATCH);
    dim3 block(256);

    // Stage 1: A = X (batched), B = T (broadcast), C = tmp
    sgemm_batched<<<grid, block>>>(X, pT, pTmp,
                                   (long)NMAT * NMAT, 0L);
    // Stage 2: A = T^T (broadcast), B = tmp (batched), C = out
    sgemm_batched<<<grid, block>>>(pTt, pTmp, out,
                                   0L, (long)NMAT * NMAT);
}

// round 4
// speedup vs baseline: 1.6355x; 1.6355x over previous
#include <cuda_runtime.h>
#include <cuda_bf16.h>
#include <cstdint>

#define N512 512
#define NBATCH 96
#define NN (N512 * N512)

// ---------------- device scratch (no allocations allowed) ----------------
__device__ float g_T[NN];                      // T[k][n]
__device__ float g_Tt[NN];                     // T^T
__device__ float g_tmp[(size_t)NBATCH * NN];   // stage-1 output (fp32)

// ---------------- helpers ----------------
__device__ __forceinline__ uint32_t smem_u32(const void* p) {
    uint32_t a;
    asm("{ .reg .u64 t; cvta.to.shared.u64 t, %1; cvt.u32.u64 %0, t; }"
        : "=r"(a) : "l"(p));
    return a;
}

#define LDSM_X4(r0, r1, r2, r3, addr)                                   \
    asm volatile("ldmatrix.sync.aligned.m8n8.x4.shared.b16 "            \
                 "{%0,%1,%2,%3}, [%4];"                                 \
                 : "=r"(r0), "=r"(r1), "=r"(r2), "=r"(r3) : "r"(addr))

#define LDSM_X4T(r0, r1, r2, r3, addr)                                  \
    asm volatile("ldmatrix.sync.aligned.m8n8.x4.trans.shared.b16 "      \
                 "{%0,%1,%2,%3}, [%4];"                                 \
                 : "=r"(r0), "=r"(r1), "=r"(r2), "=r"(r3) : "r"(addr))

#define MMA_BF16(c, a, b)                                               \
    asm volatile("mma.sync.aligned.m16n8k16.row.col.f32.bf16.bf16.f32 " \
                 "{%0,%1,%2,%3}, {%4,%5,%6,%7}, {%8,%9}, {%0,%1,%2,%3};"\
                 : "+f"((c)[0]), "+f"((c)[1]), "+f"((c)[2]), "+f"((c)[3])\
                 : "r"((a)[0]), "r"((a)[1]), "r"((a)[2]), "r"((a)[3]),  \
                   "r"((b)[0]), "r"((b)[1]))

__device__ __forceinline__ void splitpack(float a, float b,
                                          uint32_t& hp, uint32_t& lp) {
    __nv_bfloat16 ha = __float2bfloat16(a);
    __nv_bfloat16 hb = __float2bfloat16(b);
    __nv_bfloat16 la = __float2bfloat16(a - __bfloat162float(ha));
    __nv_bfloat16 lb = __float2bfloat16(b - __bfloat162float(hb));
    hp = ((uint32_t)__bfloat16_as_ushort(hb) << 16) | __bfloat16_as_ushort(ha);
    lp = ((uint32_t)__bfloat16_as_ushort(lb) << 16) | __bfloat16_as_ushort(la);
}

// ---------------- basis build ----------------
__global__ void build_basis(float* __restrict__ T, float* __restrict__ Tt) {
    int k = blockIdx.x, n = threadIdx.x;
    float ck = (k == 0) ? rsqrtf(512.0f) : sqrtf(2.0f / 512.0f);
    float v = ck * cospif((float)(k * (2 * n + 1)) * (1.0f / 1024.0f));
    T[k * N512 + n]  = v;
    Tt[n * N512 + k] = v;
}

// ---------------- GEMM: C_z = A_z @ B_z (all 512x512 row-major fp32) -------
// 3-pass bf16 split: C = Ah*Bh + Ah*Bl + Al*Bh (fp32 accum).
// CTA tile 128x128, BK=32, 8 warps (2x4), warp tile 64x32.
#define SA 40    // As padded stride (bf16 elems)
#define SB 136   // Bs padded stride

__global__ __launch_bounds__(256, 1)
void gemm_split(const float* __restrict__ Abase,
                const float* __restrict__ Bbase,
                float* __restrict__ Cbase,
                long strideA, long strideB) {
    __shared__ __align__(16) uint16_t As_h[128 * SA];
    __shared__ __align__(16) uint16_t As_l[128 * SA];
    __shared__ __align__(16) uint16_t Bs_h[32 * SB];
    __shared__ __align__(16) uint16_t Bs_l[32 * SB];

    const int tid  = threadIdx.x;
    const int lane = tid & 31;
    const int wid  = tid >> 5;
    const int warpM = wid & 1;      // 0..1  (64-row slabs)
    const int warpN = wid >> 1;     // 0..3  (32-col slabs)

    const float* A = Abase + (long)blockIdx.z * strideA;
    const float* B = Bbase + (long)blockIdx.z * strideB;
    float* C       = Cbase + (long)blockIdx.z * (long)NN;

    const int tileM = blockIdx.y * 128;
    const int tileN = blockIdx.x * 128;

    // global load coords
    const int arow = tid >> 3;          // 0..31 (+32*rt)
    const int acol = (tid & 7) * 4;     // 0..28
    const int brow = tid >> 5;          // 0..7  (+8*rt)
    const int bcol = (tid & 31) * 4;    // 0..124

    // ldmatrix lane addressing
    const uint32_t aBaseH = smem_u32(As_h);
    const uint32_t aBaseL = smem_u32(As_l);
    const uint32_t bBaseH = smem_u32(Bs_h);
    const uint32_t bBaseL = smem_u32(Bs_l);

    uint32_t aOff[4], bOff[2];
    {
        int r = warpM * 64 + (lane & 15);
        int c = (lane >> 4) * 8;
        #pragma unroll
        for (int mt = 0; mt < 4; ++mt)
            aOff[mt] = (uint32_t)(((r + mt * 16) * SA + c) * 2);
        int rb = (lane & 7) + ((lane >> 3) & 1) * 8;
        int cb = warpN * 32 + ((lane >> 4) & 1) * 8;
        #pragma unroll
        for (int np = 0; np < 2; ++np)
            bOff[np] = (uint32_t)((rb * SB + cb + np * 16) * 2);
    }

    float acc[4][4][4] = {};
    float4 ra[4], rb[4];

    // prefetch chunk 0
    #pragma unroll
    for (int rt = 0; rt < 4; ++rt) {
        ra[rt] = *reinterpret_cast<const float4*>(
            &A[(long)(tileM + arow + rt * 32) * N512 + acol]);
        rb[rt] = *reinterpret_cast<const float4*>(
            &B[(long)(brow + rt * 8) * N512 + tileN + bcol]);
    }

    for (int ch = 0; ch < 16; ++ch) {
        __syncthreads();
        // stage (split fp32 -> bf16 hi/lo) into SMEM
        #pragma unroll
        for (int rt = 0; rt < 4; ++rt) {
            uint32_t h0, l0, h1, l1;
            splitpack(ra[rt].x, ra[rt].y, h0, l0);
            splitpack(ra[rt].z, ra[rt].w, h1, l1);
            int o = (arow + rt * 32) * SA + acol;
            *reinterpret_cast<uint2*>(&As_h[o]) = make_uint2(h0, h1);
            *reinterpret_cast<uint2*>(&As_l[o]) = make_uint2(l0, l1);
            splitpack(rb[rt].x, rb[rt].y, h0, l0);
            splitpack(rb[rt].z, rb[rt].w, h1, l1);
            o = (brow + rt * 8) * SB + bcol;
            *reinterpret_cast<uint2*>(&Bs_h[o]) = make_uint2(h0, h1);
            *reinterpret_cast<uint2*>(&Bs_l[o]) = make_uint2(l0, l1);
        }
        __syncthreads();

        // prefetch next chunk (overlaps with compute below)
        if (ch < 15) {
            int k0 = (ch + 1) * 32;
            #pragma unroll
            for (int rt = 0; rt < 4; ++rt) {
                ra[rt] = *reinterpret_cast<const float4*>(
                    &A[(long)(tileM + arow + rt * 32) * N512 + k0 + acol]);
                rb[rt] = *reinterpret_cast<const float4*>(
                    &B[(long)(k0 + brow + rt * 8) * N512 + tileN + bcol]);
            }
        }

        // compute 2 x k16 steps
        #pragma unroll
        for (int ks = 0; ks < 2; ++ks) {
            uint32_t ah[4][4], al[4][4], bh[4][2], bl[4][2];
            #pragma unroll
            for (int mt = 0; mt < 4; ++mt) {
                uint32_t ad = aOff[mt] + ks * 32;
                LDSM_X4(ah[mt][0], ah[mt][1], ah[mt][2], ah[mt][3], aBaseH + ad);
                LDSM_X4(al[mt][0], al[mt][1], al[mt][2], al[mt][3], aBaseL + ad);
            }
            #pragma unroll
            for (int np = 0; np < 2; ++np) {
                uint32_t bd = bOff[np] + ks * (16 * SB * 2);
                uint32_t t0, t1, t2, t3;
                LDSM_X4T(t0, t1, t2, t3, bBaseH + bd);
                bh[2 * np][0] = t0; bh[2 * np][1] = t1;
                bh[2 * np + 1][0] = t2; bh[2 * np + 1][1] = t3;
                LDSM_X4T(t0, t1, t2, t3, bBaseL + bd);
                bl[2 * np][0] = t0; bl[2 * np][1] = t1;
                bl[2 * np + 1][0] = t2; bl[2 * np + 1][1] = t3;
            }
            #pragma unroll
            for (int mt = 0; mt < 4; ++mt)
                #pragma unroll
                for (int nt = 0; nt < 4; ++nt) {
                    MMA_BF16(acc[mt][nt], ah[mt], bh[nt]);
                    MMA_BF16(acc[mt][nt], ah[mt], bl[nt]);
                    MMA_BF16(acc[mt][nt], al[mt], bh[nt]);
                }
        }
    }

    // epilogue: direct fp32 stores (float2 per row-half)
    #pragma unroll
    for (int mt = 0; mt < 4; ++mt) {
        int r0 = tileM + warpM * 64 + mt * 16 + (lane >> 2);
        #pragma unroll
        for (int nt = 0; nt < 4; ++nt) {
            int c0 = tileN + warpN * 32 + nt * 8 + (lane & 3) * 2;
            *reinterpret_cast<float2*>(&C[(long)r0 * N512 + c0]) =
                make_float2(acc[mt][nt][0], acc[mt][nt][1]);
            *reinterpret_cast<float2*>(&C[(long)(r0 + 8) * N512 + c0]) =
                make_float2(acc[mt][nt][2], acc[mt][nt][3]);
        }
    }
}

// ---------------- host launcher ----------------
extern "C" void kernel_launch(void* const* d_in, const int* in_sizes, int n_in,
                              void* d_out, int out_size) {
    const float* X = (const float*)d_in[0];
    float* out = (float*)d_out;

    float *pT, *pTt, *pTmp;
    cudaGetSymbolAddress((void**)&pT,   g_T);
    cudaGetSymbolAddress((void**)&pTt,  g_Tt);
    cudaGetSymbolAddress((void**)&pTmp, g_tmp);

    build_basis<<<N512, N512>>>(pT, pTt);

    dim3 grid(4, 4, NBATCH);
    // stage 1: C1 = X @ T
    gemm_split<<<grid, 256>>>(X, pT, pTmp, (long)NN, 0L);
    // stage 2: Out = T^T @ C1
    gemm_split<<<grid, 256>>>(pTt, pTmp, out, 0L, (long)NN);
}

// round 5
// speedup vs baseline: 2.2732x; 1.3899x over previous
#include <cuda_runtime.h>
#include <cuda_bf16.h>
#include <cstdint>

#define N512 512
#define NBATCH 96
#define NN (N512 * N512)
#define NELEM ((size_t)NBATCH * NN)   // 25,165,824

// ---------------- device scratch (no allocations allowed) ----------------
__device__ __nv_bfloat16 g_Xh[NELEM];
__device__ __nv_bfloat16 g_Xl[NELEM];
__device__ __nv_bfloat16 g_tmpH[NELEM];
__device__ __nv_bfloat16 g_tmpL[NELEM];
__device__ __nv_bfloat16 g_Th[NN],  g_Tl[NN];    // T[k][n] hi/lo
__device__ __nv_bfloat16 g_Tth[NN], g_Ttl[NN];   // T^T[i][k] hi/lo

// ---------------- helpers ----------------
__device__ __forceinline__ uint32_t smem_u32(const void* p) {
    uint32_t a;
    asm("{ .reg .u64 t; cvta.to.shared.u64 t, %1; cvt.u32.u64 %0, t; }"
        : "=r"(a) : "l"(p));
    return a;
}

#define LDSM_X4(r0, r1, r2, r3, addr)                                   \
    asm volatile("ldmatrix.sync.aligned.m8n8.x4.shared.b16 "            \
                 "{%0,%1,%2,%3}, [%4];"                                 \
                 : "=r"(r0), "=r"(r1), "=r"(r2), "=r"(r3) : "r"(addr))

#define LDSM_X4T(r0, r1, r2, r3, addr)                                  \
    asm volatile("ldmatrix.sync.aligned.m8n8.x4.trans.shared.b16 "      \
                 "{%0,%1,%2,%3}, [%4];"                                 \
                 : "=r"(r0), "=r"(r1), "=r"(r2), "=r"(r3) : "r"(addr))

#define MMA_BF16(c, a, b)                                               \
    asm volatile("mma.sync.aligned.m16n8k16.row.col.f32.bf16.bf16.f32 " \
                 "{%0,%1,%2,%3}, {%4,%5,%6,%7}, {%8,%9}, {%0,%1,%2,%3};"\
                 : "+f"((c)[0]), "+f"((c)[1]), "+f"((c)[2]), "+f"((c)[3])\
                 : "r"((a)[0]), "r"((a)[1]), "r"((a)[2]), "r"((a)[3]),  \
                   "r"((b)[0]), "r"((b)[1]))

#define CP_ASYNC16(dst, src)                                            \
    asm volatile("cp.async.cg.shared.global [%0], [%1], 16;"            \
                 :: "r"(dst), "l"(src))
#define CP_COMMIT()  asm volatile("cp.async.commit_group;")
#define CP_WAIT1()   asm volatile("cp.async.wait_group 1;")

__device__ __forceinline__ void splitpack(float a, float b,
                                          uint32_t& hp, uint32_t& lp) {
    __nv_bfloat16 ha = __float2bfloat16(a);
    __nv_bfloat16 hb = __float2bfloat16(b);
    __nv_bfloat16 la = __float2bfloat16(a - __bfloat162float(ha));
    __nv_bfloat16 lb = __float2bfloat16(b - __bfloat162float(hb));
    hp = ((uint32_t)__bfloat16_as_ushort(hb) << 16) | __bfloat16_as_ushort(ha);
    lp = ((uint32_t)__bfloat16_as_ushort(lb) << 16) | __bfloat16_as_ushort(la);
}

// ---------------- prep: split X into bf16 hi/lo ----------------
__global__ __launch_bounds__(256)
void split_X(const float4* __restrict__ X,
             uint2* __restrict__ Hi, uint2* __restrict__ Lo) {
    size_t i = (size_t)blockIdx.x * 256 + threadIdx.x;   // float4 index
    if (i >= NELEM / 4) return;
    float4 v = X[i];
    uint32_t h0, l0, h1, l1;
    splitpack(v.x, v.y, h0, l0);
    splitpack(v.z, v.w, h1, l1);
    Hi[i] = make_uint2(h0, h1);
    Lo[i] = make_uint2(l0, l1);
}

// ---------------- basis build (split) ----------------
__global__ void build_basis(__nv_bfloat16* __restrict__ Th, __nv_bfloat16* __restrict__ Tl,
                            __nv_bfloat16* __restrict__ Tth, __nv_bfloat16* __restrict__ Ttl) {
    int k = blockIdx.x, n = threadIdx.x;
    float ck = (k == 0) ? rsqrtf(512.0f) : sqrtf(2.0f / 512.0f);
    float v = ck * cospif((float)(k * (2 * n + 1)) * (1.0f / 1024.0f));
    __nv_bfloat16 h = __float2bfloat16(v);
    __nv_bfloat16 l = __float2bfloat16(v - __bfloat162float(h));
    Th[k * N512 + n] = h;  Tl[k * N512 + n] = l;
    Tth[n * N512 + k] = h; Ttl[n * N512 + k] = l;
}

// ---------------- SMEM layout (dynamic, bytes) ----------------
// A tile: 128 rows x 64 bf16 (128B data) padded to 144B/row  -> 18432 B
// B tile:  64 rows x 128 bf16 (256B data) padded to 272B/row -> 17408 B
// per buffer: Ah | Al | Bh | Bl = 71680 B ; two buffers = 143360 B
#define A_STRIDE 144
#define B_STRIDE 272
#define A_TILE   18432
#define B_TILE   17408
#define BUF_B    71680
#define SMEM_TOTAL (2 * BUF_B)

// ---------------- GEMM: C_z = A_z @ B_z, operands pre-split bf16 ----------
// A: row-major [M][K] (K contiguous). B: [K][N] (N contiguous).
// C = Ah*Bh + Ah*Bl + Al*Bh with fp32 accum. CTA 128x128, BK=64, 8 warps.
template <bool STAGE2>
__global__ __launch_bounds__(256, 1)
void gemm_split(const __nv_bfloat16* __restrict__ AhG, const __nv_bfloat16* __restrict__ AlG,
                const __nv_bfloat16* __restrict__ BhG, const __nv_bfloat16* __restrict__ BlG,
                __nv_bfloat16* __restrict__ OutH, __nv_bfloat16* __restrict__ OutL,
                float* __restrict__ OutF,
                long strideA, long strideB) {
    extern __shared__ __align__(16) char sm[];
    const uint32_t smb = smem_u32(sm);

    const int tid  = threadIdx.x;
    const int lane = tid & 31;
    const int wid  = tid >> 5;
    const int warpM = wid & 1;
    const int warpN = wid >> 1;

    const __nv_bfloat16* Ah = AhG + (long)blockIdx.z * strideA;
    const __nv_bfloat16* Al = AlG + (long)blockIdx.z * strideA;
    const __nv_bfloat16* Bh = BhG + (long)blockIdx.z * strideB;
    const __nv_bfloat16* Bl = BlG + (long)blockIdx.z * strideB;

    const int tileM = blockIdx.y * 128;
    const int tileN = blockIdx.x * 128;

    // ---- cp.async staging of one chunk into one buffer ----
    auto issue = [&](int k0, int buf) {
        const uint32_t base = smb + buf * BUF_B;
        // A: 128 rows x 128B -> 1024 x 16B units, 4 per thread
        #pragma unroll
        for (int i = 0; i < 4; ++i) {
            int u = tid + i * 256;
            int row = u >> 3;
            int c16 = u & 7;
            uint32_t dst = base + row * A_STRIDE + c16 * 16;
            const __nv_bfloat16* sh = &Ah[(long)(tileM + row) * N512 + k0 + c16 * 8];
            const __nv_bfloat16* sl = &Al[(long)(tileM + row) * N512 + k0 + c16 * 8];
            CP_ASYNC16(dst, sh);
            CP_ASYNC16(dst + A_TILE, sl);
        }
        // B: 64 rows x 256B -> 1024 x 16B units, 4 per thread
        #pragma unroll
        for (int i = 0; i < 4; ++i) {
            int u = tid + i * 256;
            int row = u >> 4;
            int c16 = u & 15;
            uint32_t dst = base + 2 * A_TILE + row * B_STRIDE + c16 * 16;
            const __nv_bfloat16* sh = &Bh[(long)(k0 + row) * N512 + tileN + c16 * 8];
            const __nv_bfloat16* sl = &Bl[(long)(k0 + row) * N512 + tileN + c16 * 8];
            CP_ASYNC16(dst, sh);
            CP_ASYNC16(dst + B_TILE, sl);
        }
        CP_COMMIT();
    };

    float acc[4][4][4] = {};

    // lane addressing (bytes)
    const int aRow = lane & 15;
    const int aCol = (lane >> 4) * 16;
    const int bRow = lane & 15;
    const int bCol = warpN * 64 + (lane >> 4) * 16;

    // prologue: chunks 0,1
    issue(0, 0);
    issue(64, 1);

    for (int c = 0; c < 8; ++c) {
        const int buf = c & 1;
        CP_WAIT1();
        __syncthreads();

        const uint32_t bA  = smb + buf * BUF_B;
        const uint32_t bB  = bA + 2 * A_TILE;

        #pragma unroll
        for (int ks = 0; ks < 4; ++ks) {
            uint32_t ah[4][4], al[4][4], bh[4][2], bl[4][2];
            #pragma unroll
            for (int mt = 0; mt < 4; ++mt) {
                uint32_t ad = bA + (warpM * 64 + mt * 16 + aRow) * A_STRIDE
                            + aCol + ks * 32;
                LDSM_X4(ah[mt][0], ah[mt][1], ah[mt][2], ah[mt][3], ad);
                LDSM_X4(al[mt][0], al[mt][1], al[mt][2], al[mt][3], ad + A_TILE);
            }
            #pragma unroll
            for (int np = 0; np < 2; ++np) {
                uint32_t bd = bB + (ks * 16 + bRow) * B_STRIDE + bCol + np * 32;
                uint32_t t0, t1, t2, t3;
                LDSM_X4T(t0, t1, t2, t3, bd);
                bh[2 * np][0] = t0; bh[2 * np][1] = t1;
                bh[2 * np + 1][0] = t2; bh[2 * np + 1][1] = t3;
                LDSM_X4T(t0, t1, t2, t3, bd + B_TILE);
                bl[2 * np][0] = t0; bl[2 * np][1] = t1;
                bl[2 * np + 1][0] = t2; bl[2 * np + 1][1] = t3;
            }
            #pragma unroll
            for (int mt = 0; mt < 4; ++mt)
                #pragma unroll
                for (int nt = 0; nt < 4; ++nt) {
                    MMA_BF16(acc[mt][nt], ah[mt], bh[nt]);
                    MMA_BF16(acc[mt][nt], ah[mt], bl[nt]);
                    MMA_BF16(acc[mt][nt], al[mt], bh[nt]);
                }
        }

        __syncthreads();
        if (c + 2 < 8) issue((c + 2) * 64, buf);
        else           CP_COMMIT();           // keep group arithmetic aligned
    }

    // ---------------- epilogue ----------------
    const long imgC = (long)blockIdx.z * NN;
    #pragma unroll
    for (int mt = 0; mt < 4; ++mt) {
        int r0 = tileM + warpM * 64 + mt * 16 + (lane >> 2);
        #pragma unroll
        for (int nt = 0; nt < 4; ++nt) {
            int c0 = tileN + warpN * 32 + nt * 8 + (lane & 3) * 2;
            if (!STAGE2) {
                uint32_t hp, lp;
                splitpack(acc[mt][nt][0], acc[mt][nt][1], hp, lp);
                *reinterpret_cast<uint32_t*>(&OutH[imgC + (long)r0 * N512 + c0]) = hp;
                *reinterpret_cast<uint32_t*>(&OutL[imgC + (long)r0 * N512 + c0]) = lp;
                splitpack(acc[mt][nt][2], acc[mt][nt][3], hp, lp);
                *reinterpret_cast<uint32_t*>(&OutH[imgC + (long)(r0 + 8) * N512 + c0]) = hp;
                *reinterpret_cast<uint32_t*>(&OutL[imgC + (long)(r0 + 8) * N512 + c0]) = lp;
            } else {
                *reinterpret_cast<float2*>(&OutF[imgC + (long)r0 * N512 + c0]) =
                    make_float2(acc[mt][nt][0], acc[mt][nt][1]);
                *reinterpret_cast<float2*>(&OutF[imgC + (long)(r0 + 8) * N512 + c0]) =
                    make_float2(acc[mt][nt][2], acc[mt][nt][3]);
            }
        }
    }
}

// ---------------- host launcher ----------------
extern "C" void kernel_launch(void* const* d_in, const int* in_sizes, int n_in,
                              void* d_out, int out_size) {
    const float* X = (const float*)d_in[0];
    float* out = (float*)d_out;

    __nv_bfloat16 *pXh, *pXl, *pTmpH, *pTmpL, *pTh, *pTl, *pTth, *pTtl;
    cudaGetSymbolAddress((void**)&pXh,   g_Xh);
    cudaGetSymbolAddress((void**)&pXl,   g_Xl);
    cudaGetSymbolAddress((void**)&pTmpH, g_tmpH);
    cudaGetSymbolAddress((void**)&pTmpL, g_tmpL);
    cudaGetSymbolAddress((void**)&pTh,   g_Th);
    cudaGetSymbolAddress((void**)&pTl,   g_Tl);
    cudaGetSymbolAddress((void**)&pTth,  g_Tth);
    cudaGetSymbolAddress((void**)&pTtl,  g_Ttl);

    cudaFuncSetAttribute(gemm_split<false>, cudaFuncAttributeMaxDynamicSharedMemorySize, SMEM_TOTAL);
    cudaFuncSetAttribute(gemm_split<true>,  cudaFuncAttributeMaxDynamicSharedMemorySize, SMEM_TOTAL);

    build_basis<<<N512, N512>>>(pTh, pTl, pTth, pTtl);
    split_X<<<(int)(NELEM / 4 / 256), 256>>>((const float4*)X, (uint2*)pXh, (uint2*)pXl);

    dim3 grid(4, 4, NBATCH);
    // stage 1: C1 = X @ T     (A = X hi/lo batched, B = T hi/lo broadcast)
    gemm_split<false><<<grid, 256, SMEM_TOTAL>>>(pXh, pXl, pTh, pTl,
                                                 pTmpH, pTmpL, nullptr,
                                                 (long)NN, 0L);
    // stage 2: Out = T^T @ C1 (A = Tt hi/lo broadcast, B = C1 hi/lo batched)
    gemm_split<true><<<grid, 256, SMEM_TOTAL>>>(pTth, pTtl, pTmpH, pTmpL,
                                                nullptr, nullptr, out,
                                                0L, (long)NN);
}

// round 6
// speedup vs baseline: 2.5349x; 1.1152x over previous
#include <cuda_runtime.h>
#include <cuda_bf16.h>
#include <cstdint>

#define N512 512
#define NBATCH 96
#define NN (N512 * N512)
#define NELEM ((size_t)NBATCH * NN)   // 25,165,824

// ---------------- device scratch (no allocations allowed) ----------------
__device__ __nv_bfloat16 g_Xh[NELEM];
__device__ __nv_bfloat16 g_Xl[NELEM];
__device__ __nv_bfloat16 g_tmpH[NELEM];
__device__ __nv_bfloat16 g_tmpL[NELEM];
__device__ __nv_bfloat16 g_Th[NN],  g_Tl[NN];    // T[k][n] hi/lo
__device__ __nv_bfloat16 g_Tth[NN], g_Ttl[NN];   // T^T[i][k] hi/lo

// ---------------- helpers ----------------
__device__ __forceinline__ uint32_t smem_u32(const void* p) {
    uint32_t a;
    asm("{ .reg .u64 t; cvta.to.shared.u64 t, %1; cvt.u32.u64 %0, t; }"
        : "=r"(a) : "l"(p));
    return a;
}

#define LDSM_X4(r0, r1, r2, r3, addr)                                   \
    asm volatile("ldmatrix.sync.aligned.m8n8.x4.shared.b16 "            \
                 "{%0,%1,%2,%3}, [%4];"                                 \
                 : "=r"(r0), "=r"(r1), "=r"(r2), "=r"(r3) : "r"(addr))

#define LDSM_X4T(r0, r1, r2, r3, addr)                                  \
    asm volatile("ldmatrix.sync.aligned.m8n8.x4.trans.shared.b16 "      \
                 "{%0,%1,%2,%3}, [%4];"                                 \
                 : "=r"(r0), "=r"(r1), "=r"(r2), "=r"(r3) : "r"(addr))

#define MMA_BF16(c, a, b)                                               \
    asm volatile("mma.sync.aligned.m16n8k16.row.col.f32.bf16.bf16.f32 " \
                 "{%0,%1,%2,%3}, {%4,%5,%6,%7}, {%8,%9}, {%0,%1,%2,%3};"\
                 : "+f"((c)[0]), "+f"((c)[1]), "+f"((c)[2]), "+f"((c)[3])\
                 : "r"((a)[0]), "r"((a)[1]), "r"((a)[2]), "r"((a)[3]),  \
                   "r"((b)[0]), "r"((b)[1]))

#define CP_ASYNC16(dst, src)                                            \
    asm volatile("cp.async.cg.shared.global [%0], [%1], 16;"            \
                 :: "r"(dst), "l"(src))
#define CP_COMMIT()  asm volatile("cp.async.commit_group;")
#define CP_WAIT1()   asm volatile("cp.async.wait_group 1;")

__device__ __forceinline__ void splitpack(float a, float b,
                                          uint32_t& hp, uint32_t& lp) {
    __nv_bfloat16 ha = __float2bfloat16(a);
    __nv_bfloat16 hb = __float2bfloat16(b);
    __nv_bfloat16 la = __float2bfloat16(a - __bfloat162float(ha));
    __nv_bfloat16 lb = __float2bfloat16(b - __bfloat162float(hb));
    hp = ((uint32_t)__bfloat16_as_ushort(hb) << 16) | __bfloat16_as_ushort(ha);
    lp = ((uint32_t)__bfloat16_as_ushort(lb) << 16) | __bfloat16_as_ushort(la);
}

// ---------------- prep kernels ----------------
__global__ __launch_bounds__(256)
void split_X(const float4* __restrict__ X,
             uint2* __restrict__ Hi, uint2* __restrict__ Lo) {
    size_t i = (size_t)blockIdx.x * 256 + threadIdx.x;
    if (i >= NELEM / 4) return;
    float4 v = X[i];
    uint32_t h0, l0, h1, l1;
    splitpack(v.x, v.y, h0, l0);
    splitpack(v.z, v.w, h1, l1);
    Hi[i] = make_uint2(h0, h1);
    Lo[i] = make_uint2(l0, l1);
}

__global__ void build_basis(__nv_bfloat16* __restrict__ Th, __nv_bfloat16* __restrict__ Tl,
                            __nv_bfloat16* __restrict__ Tth, __nv_bfloat16* __restrict__ Ttl) {
    int k = blockIdx.x, n = threadIdx.x;
    float ck = (k == 0) ? rsqrtf(512.0f) : sqrtf(2.0f / 512.0f);
    float v = ck * cospif((float)(k * (2 * n + 1)) * (1.0f / 1024.0f));
    __nv_bfloat16 h = __float2bfloat16(v);
    __nv_bfloat16 l = __float2bfloat16(v - __bfloat162float(h));
    Th[k * N512 + n] = h;  Tl[k * N512 + n] = l;
    Tth[n * N512 + k] = h; Ttl[n * N512 + k] = l;
}

// ---------------- SMEM layout (bytes) ----------------
// BK = 32. A tile: 128 rows x 32 bf16 (64B) pad-> 80B/row  = 10240 B
//          B tile:  32 rows x 128 bf16 (256B) pad-> 272B/row =  8704 B
// stage: Ah | Al | Bh | Bl = 37888 B ; 3 stages = 113664 B (2 CTAs/SM)
#define A_STRIDE 80
#define B_STRIDE 272
#define A_TILE   10240
#define B_TILE   8704
#define STAGE_B  37888
#define SMEM_TOTAL (3 * STAGE_B)

// ---------------- GEMM: C = Ah*Bh + Ah*Bl + Al*Bh (fp32 acc) --------------
// CTA 128x128, BK=32, 16 chunks, 3-stage cp.async, 8 warps, warp tile 64x32.
template <bool STAGE2>
__global__ __launch_bounds__(256, 2)
void gemm_split(const __nv_bfloat16* __restrict__ AhG, const __nv_bfloat16* __restrict__ AlG,
                const __nv_bfloat16* __restrict__ BhG, const __nv_bfloat16* __restrict__ BlG,
                __nv_bfloat16* __restrict__ OutH, __nv_bfloat16* __restrict__ OutL,
                float* __restrict__ OutF,
                long strideA, long strideB) {
    extern __shared__ __align__(16) char sm[];
    const uint32_t smb = smem_u32(sm);

    const int tid  = threadIdx.x;
    const int lane = tid & 31;
    const int wid  = tid >> 5;
    const int warpM = wid & 1;
    const int warpN = wid >> 1;

    const __nv_bfloat16* Ah = AhG + (long)blockIdx.z * strideA;
    const __nv_bfloat16* Al = AlG + (long)blockIdx.z * strideA;
    const __nv_bfloat16* Bh = BhG + (long)blockIdx.z * strideB;
    const __nv_bfloat16* Bl = BlG + (long)blockIdx.z * strideB;

    const int tileM = blockIdx.y * 128;
    const int tileN = blockIdx.x * 128;

    // cp.async staging: A 512x16B units (2/thread), B 512x16B units (2/thread)
    const int aRowL = tid >> 1;            // +64 per i   (row 0..127)
    const int aC16  = (tid & 1) * 2;       // 16B unit 0 or 2 (load 2 units? no)
    // simpler: u = tid + i*256 ; row=u>>2 ; c16=u&3
    auto issue = [&](int k0, int buf) {
        const uint32_t base = smb + buf * STAGE_B;
        #pragma unroll
        for (int i = 0; i < 2; ++i) {
            int u = tid + i * 256;
            int row = u >> 2;
            int c16 = u & 3;
            uint32_t dst = base + row * A_STRIDE + c16 * 16;
            CP_ASYNC16(dst,          &Ah[(long)(tileM + row) * N512 + k0 + c16 * 8]);
            CP_ASYNC16(dst + A_TILE, &Al[(long)(tileM + row) * N512 + k0 + c16 * 8]);
        }
        #pragma unroll
        for (int i = 0; i < 2; ++i) {
            int u = tid + i * 256;
            int row = u >> 4;
            int c16 = u & 15;
            uint32_t dst = base + 2 * A_TILE + row * B_STRIDE + c16 * 16;
            CP_ASYNC16(dst,          &Bh[(long)(k0 + row) * N512 + tileN + c16 * 8]);
            CP_ASYNC16(dst + B_TILE, &Bl[(long)(k0 + row) * N512 + tileN + c16 * 8]);
        }
        CP_COMMIT();
    };

    float acc[4][4][4] = {};

    // ldmatrix lane addressing (bytes, relative to stage base)
    const uint32_t aAddr0 = (uint32_t)((warpM * 64 + (lane & 15)) * A_STRIDE
                                       + (lane >> 4) * 16);
    const uint32_t bAddr0 = (uint32_t)(2 * A_TILE + (lane & 15) * B_STRIDE
                                       + warpN * 64 + (lane >> 4) * 16);

    issue(0, 0);
    issue(32, 1);

    for (int c = 0; c < 16; ++c) {
        const int buf = c % 3;
        CP_WAIT1();
        __syncthreads();
        if (c + 2 < 16) issue((c + 2) * 32, (c + 2) % 3);
        else            CP_COMMIT();

        const uint32_t sb = smb + buf * STAGE_B;

        #pragma unroll
        for (int ks = 0; ks < 2; ++ks) {
            uint32_t a_[4][4], bh_[4][2], bo_[4][2];
            // load Ah fragments
            #pragma unroll
            for (int mt = 0; mt < 4; ++mt) {
                uint32_t ad = sb + aAddr0 + mt * (16 * A_STRIDE) + ks * 32;
                LDSM_X4(a_[mt][0], a_[mt][1], a_[mt][2], a_[mt][3], ad);
            }
            // load Bh fragments
            #pragma unroll
            for (int np = 0; np < 2; ++np) {
                uint32_t bd = sb + bAddr0 + ks * (16 * B_STRIDE) + np * 32;
                uint32_t t0, t1, t2, t3;
                LDSM_X4T(t0, t1, t2, t3, bd);
                bh_[2 * np][0] = t0;     bh_[2 * np][1] = t1;
                bh_[2 * np + 1][0] = t2; bh_[2 * np + 1][1] = t3;
            }
            // pass 1: Ah * Bh
            #pragma unroll
            for (int mt = 0; mt < 4; ++mt)
                #pragma unroll
                for (int nt = 0; nt < 4; ++nt)
                    MMA_BF16(acc[mt][nt], a_[mt], bh_[nt]);
            // load Bl, pass 2: Ah * Bl
            #pragma unroll
            for (int np = 0; np < 2; ++np) {
                uint32_t bd = sb + bAddr0 + B_TILE + ks * (16 * B_STRIDE) + np * 32;
                uint32_t t0, t1, t2, t3;
                LDSM_X4T(t0, t1, t2, t3, bd);
                bo_[2 * np][0] = t0;     bo_[2 * np][1] = t1;
                bo_[2 * np + 1][0] = t2; bo_[2 * np + 1][1] = t3;
            }
            #pragma unroll
            for (int mt = 0; mt < 4; ++mt)
                #pragma unroll
                for (int nt = 0; nt < 4; ++nt)
                    MMA_BF16(acc[mt][nt], a_[mt], bo_[nt]);
            // load Al over Ah, pass 3: Al * Bh
            #pragma unroll
            for (int mt = 0; mt < 4; ++mt) {
                uint32_t ad = sb + aAddr0 + A_TILE + mt * (16 * A_STRIDE) + ks * 32;
                LDSM_X4(a_[mt][0], a_[mt][1], a_[mt][2], a_[mt][3], ad);
            }
            #pragma unroll
            for (int mt = 0; mt < 4; ++mt)
                #pragma unroll
                for (int nt = 0; nt < 4; ++nt)
                    MMA_BF16(acc[mt][nt], a_[mt], bh_[nt]);
        }
        __syncthreads();
    }

    // ---------------- epilogue ----------------
    const long imgC = (long)blockIdx.z * NN;
    #pragma unroll
    for (int mt = 0; mt < 4; ++mt) {
        int r0 = tileM + warpM * 64 + mt * 16 + (lane >> 2);
        #pragma unroll
        for (int nt = 0; nt < 4; ++nt) {
            int c0 = tileN + warpN * 32 + nt * 8 + (lane & 3) * 2;
            if (!STAGE2) {
                uint32_t hp, lp;
                splitpack(acc[mt][nt][0], acc[mt][nt][1], hp, lp);
                *reinterpret_cast<uint32_t*>(&OutH[imgC + (long)r0 * N512 + c0]) = hp;
                *reinterpret_cast<uint32_t*>(&OutL[imgC + (long)r0 * N512 + c0]) = lp;
                splitpack(acc[mt][nt][2], acc[mt][nt][3], hp, lp);
                *reinterpret_cast<uint32_t*>(&OutH[imgC + (long)(r0 + 8) * N512 + c0]) = hp;
                *reinterpret_cast<uint32_t*>(&OutL[imgC + (long)(r0 + 8) * N512 + c0]) = lp;
            } else {
                *reinterpret_cast<float2*>(&OutF[imgC + (long)r0 * N512 + c0]) =
                    make_float2(acc[mt][nt][0], acc[mt][nt][1]);
                *reinterpret_cast<float2*>(&OutF[imgC + (long)(r0 + 8) * N512 + c0]) =
                    make_float2(acc[mt][nt][2], acc[mt][nt][3]);
            }
        }
    }
}

// ---------------- host launcher ----------------
extern "C" void kernel_launch(void* const* d_in, const int* in_sizes, int n_in,
                              void* d_out, int out_size) {
    const float* X = (const float*)d_in[0];
    float* out = (float*)d_out;

    __nv_bfloat16 *pXh, *pXl, *pTmpH, *pTmpL, *pTh, *pTl, *pTth, *pTtl;
    cudaGetSymbolAddress((void**)&pXh,   g_Xh);
    cudaGetSymbolAddress((void**)&pXl,   g_Xl);
    cudaGetSymbolAddress((void**)&pTmpH, g_tmpH);
    cudaGetSymbolAddress((void**)&pTmpL, g_tmpL);
    cudaGetSymbolAddress((void**)&pTh,   g_Th);
    cudaGetSymbolAddress((void**)&pTl,   g_Tl);
    cudaGetSymbolAddress((void**)&pTth,  g_Tth);
    cudaGetSymbolAddress((void**)&pTtl,  g_Ttl);

    cudaFuncSetAttribute(gemm_split<false>, cudaFuncAttributeMaxDynamicSharedMemorySize, SMEM_TOTAL);
    cudaFuncSetAttribute(gemm_split<true>,  cudaFuncAttributeMaxDynamicSharedMemorySize, SMEM_TOTAL);

    build_basis<<<N512, N512>>>(pTh, pTl, pTth, pTtl);
    split_X<<<(int)(NELEM / 4 / 256), 256>>>((const float4*)X, (uint2*)pXh, (uint2*)pXl);

    dim3 grid(4, 4, NBATCH);
    gemm_split<false><<<grid, 256, SMEM_TOTAL>>>(pXh, pXl, pTh, pTl,
                                                 pTmpH, pTmpL, nullptr,
                                                 (long)NN, 0L);
    gemm_split<true><<<grid, 256, SMEM_TOTAL>>>(pTth, pTtl, pTmpH, pTmpL,
                                                nullptr, nullptr, out,
                                                0L, (long)NN);
}

// round 9
// speedup vs baseline: 3.5798x; 1.4122x over previous
#include <cuda_runtime.h>
#include <cuda_fp16.h>
#include <cstdint>

#define N512 512
#define NBATCH 96
#define NN (N512 * N512)
#define NELEM ((size_t)NBATCH * NN)   // 25,165,824

// ---------------- device scratch (no allocations allowed) ----------------
__device__ __half g_Xh[NELEM];                  // X quantized fp16
__device__ __half g_tmpH[NELEM];                // stage-1 out hi
__device__ __half g_tmpL[NELEM];                // stage-1 out lo
__device__ __half g_Th[NN],  g_Tl[NN];          // T[k][n] hi/lo
__device__ __half g_Tth[NN];                    // T^T[i][k] hi (single)

// ---------------- helpers ----------------
__device__ __forceinline__ uint32_t smem_u32(const void* p) {
    uint32_t a;
    asm("{ .reg .u64 t; cvta.to.shared.u64 t, %1; cvt.u32.u64 %0, t; }"
        : "=r"(a) : "l"(p));
    return a;
}

#define LDSM_X4(r0, r1, r2, r3, addr)                                   \
    asm volatile("ldmatrix.sync.aligned.m8n8.x4.shared.b16 "            \
                 "{%0,%1,%2,%3}, [%4];"                                 \
                 : "=r"(r0), "=r"(r1), "=r"(r2), "=r"(r3) : "r"(addr))

#define LDSM_X4T(r0, r1, r2, r3, addr)                                  \
    asm volatile("ldmatrix.sync.aligned.m8n8.x4.trans.shared.b16 "      \
                 "{%0,%1,%2,%3}, [%4];"                                 \
                 : "=r"(r0), "=r"(r1), "=r"(r2), "=r"(r3) : "r"(addr))

#define MMA_F16(c, a, b)                                                \
    asm volatile("mma.sync.aligned.m16n8k16.row.col.f32.f16.f16.f32 "   \
                 "{%0,%1,%2,%3}, {%4,%5,%6,%7}, {%8,%9}, {%0,%1,%2,%3};"\
                 : "+f"((c)[0]), "+f"((c)[1]), "+f"((c)[2]), "+f"((c)[3])\
                 : "r"((a)[0]), "r"((a)[1]), "r"((a)[2]), "r"((a)[3]),  \
                   "r"((b)[0]), "r"((b)[1]))

#define CP_ASYNC16(dst, src)                                            \
    asm volatile("cp.async.cg.shared.global [%0], [%1], 16;"            \
                 :: "r"(dst), "l"(src))
#define CP_COMMIT()  asm volatile("cp.async.commit_group;")
#define CP_WAIT1()   asm volatile("cp.async.wait_group 1;")

__device__ __forceinline__ void splitpack_h(float a, float b,
                                            uint32_t& hp, uint32_t& lp) {
    __half ha = __float2half_rn(a);
    __half hb = __float2half_rn(b);
    __half la = __float2half_rn(a - __half2float(ha));
    __half lb = __float2half_rn(b - __half2float(hb));
    hp = ((uint32_t)__half_as_ushort(hb) << 16) | __half_as_ushort(ha);
    lp = ((uint32_t)__half_as_ushort(lb) << 16) | __half_as_ushort(la);
}

// ---------------- prep kernels ----------------
__global__ __launch_bounds__(256)
void quant_X(const float4* __restrict__ X, uint2* __restrict__ H) {
    size_t i = (size_t)blockIdx.x * 256 + threadIdx.x;
    if (i >= NELEM / 4) return;
    float4 v = X[i];
    __half2 p0 = __floats2half2_rn(v.x, v.y);
    __half2 p1 = __floats2half2_rn(v.z, v.w);
    H[i] = make_uint2(*reinterpret_cast<uint32_t*>(&p0),
                      *reinterpret_cast<uint32_t*>(&p1));
}

__global__ void build_basis(__half* __restrict__ Th, __half* __restrict__ Tl,
                            __half* __restrict__ Tth) {
    int k = blockIdx.x, n = threadIdx.x;
    float ck = (k == 0) ? rsqrtf(512.0f) : sqrtf(2.0f / 512.0f);
    float v = ck * cospif((float)(k * (2 * n + 1)) * (1.0f / 1024.0f));
    __half h = __float2half_rn(v);
    __half l = __float2half_rn(v - __half2float(h));
    Th[k * N512 + n] = h;
    Tl[k * N512 + n] = l;
    Tth[n * N512 + k] = h;
}

// ---------------- SMEM layout (bytes) ----------------
// BK = 32. A tile: 128 rows x 32 fp16 (64B) pad-> 80B/row  = 10240 B
//          B tile:  32 rows x 128 fp16 (256B) pad-> 272B/row = 8704 B
// stage: Ah | Bh | Bl = 27648 B ; 3 stages = 82944 B  (2 CTAs/SM)
#define A_STRIDE 80
#define B_STRIDE 272
#define A_TILE   10240
#define B_TILE   8704
#define STAGE_B  27648
#define SMEM_TOTAL (3 * STAGE_B)

// ---------------- GEMM: C = Ah*Bh + Ah*Bl (fp32 acc) ----------------------
// CTA 128x128, BK=32, 16 chunks, 3-stage cp.async, 8 warps, warp tile 64x32.
template <bool STAGE2>
__global__ __launch_bounds__(256, 2)
void gemm2p(const __half* __restrict__ AhG,
            const __half* __restrict__ BhG, const __half* __restrict__ BlG,
            __half* __restrict__ OutH, __half* __restrict__ OutL,
            float* __restrict__ OutF,
            long strideA, long strideB) {
    extern __shared__ __align__(16) char sm[];
    const uint32_t smb = smem_u32(sm);

    const int tid  = threadIdx.x;
    const int lane = tid & 31;
    const int wid  = tid >> 5;
    const int warpM = wid & 1;
    const int warpN = wid >> 1;

    const __half* Ah = AhG + (long)blockIdx.z * strideA;
    const __half* Bh = BhG + (long)blockIdx.z * strideB;
    const __half* Bl = BlG + (long)blockIdx.z * strideB;

    const int tileM = blockIdx.y * 128;
    const int tileN = blockIdx.x * 128;

    auto issue = [&](int k0, int buf) {
        const uint32_t base = smb + buf * STAGE_B;
        #pragma unroll
        for (int i = 0; i < 2; ++i) {
            int u = tid + i * 256;
            int row = u >> 2;
            int c16 = u & 3;
            uint32_t dst = base + row * A_STRIDE + c16 * 16;
            CP_ASYNC16(dst, &Ah[(long)(tileM + row) * N512 + k0 + c16 * 8]);
        }
        #pragma unroll
        for (int i = 0; i < 2; ++i) {
            int u = tid + i * 256;
            int row = u >> 4;
            int c16 = u & 15;
            uint32_t dst = base + A_TILE + row * B_STRIDE + c16 * 16;
            CP_ASYNC16(dst,          &Bh[(long)(k0 + row) * N512 + tileN + c16 * 8]);
            CP_ASYNC16(dst + B_TILE, &Bl[(long)(k0 + row) * N512 + tileN + c16 * 8]);
        }
        CP_COMMIT();
    };

    float acc[4][4][4] = {};

    // ldmatrix lane addressing (bytes, relative to stage base)
    const uint32_t aAddr0 = (uint32_t)((warpM * 64 + (lane & 15)) * A_STRIDE
                                       + (lane >> 4) * 16);
    const uint32_t bAddr0 = (uint32_t)(A_TILE + (lane & 15) * B_STRIDE
                                       + warpN * 64 + (lane >> 4) * 16);

    issue(0, 0);
    issue(32, 1);

    for (int c = 0; c < 16; ++c) {
        const int buf = c % 3;
        CP_WAIT1();
        __syncthreads();
        if (c + 2 < 16) issue((c + 2) * 32, (c + 2) % 3);
        else            CP_COMMIT();          // keep group counting aligned

        const uint32_t sb = smb + buf * STAGE_B;

        #pragma unroll
        for (int ks = 0; ks < 2; ++ks) {
            uint32_t a_[4][4], bh_[4][2], bl_[4][2];
            #pragma unroll
            for (int mt = 0; mt < 4; ++mt) {
                uint32_t ad = sb + aAddr0 + mt * (16 * A_STRIDE) + ks * 32;
                LDSM_X4(a_[mt][0], a_[mt][1], a_[mt][2], a_[mt][3], ad);
            }
            #pragma unroll
            for (int np = 0; np < 2; ++np) {
                uint32_t bd = sb + bAddr0 + ks * (16 * B_STRIDE) + np * 32;
                uint32_t t0, t1, t2, t3;
                LDSM_X4T(t0, t1, t2, t3, bd);
                bh_[2 * np][0] = t0;     bh_[2 * np][1] = t1;
                bh_[2 * np + 1][0] = t2; bh_[2 * np + 1][1] = t3;
            }
            // pass 1: Ah * Bh
            #pragma unroll
            for (int mt = 0; mt < 4; ++mt)
                #pragma unroll
                for (int nt = 0; nt < 4; ++nt)
                    MMA_F16(acc[mt][nt], a_[mt], bh_[nt]);
            // load Bl, pass 2: Ah * Bl
            #pragma unroll
            for (int np = 0; np < 2; ++np) {
                uint32_t bd = sb + bAddr0 + B_TILE + ks * (16 * B_STRIDE) + np * 32;
                uint32_t t0, t1, t2, t3;
                LDSM_X4T(t0, t1, t2, t3, bd);
                bl_[2 * np][0] = t0;     bl_[2 * np][1] = t1;
                bl_[2 * np + 1][0] = t2; bl_[2 * np + 1][1] = t3;
            }
            #pragma unroll
            for (int mt = 0; mt < 4; ++mt)
                #pragma unroll
                for (int nt = 0; nt < 4; ++nt)
                    MMA_F16(acc[mt][nt], a_[mt], bl_[nt]);
        }
        // no trailing sync needed: next chunk's top __syncthreads orders
        // buffer reuse (issue at c+1 targets the buffer read at c-1... etc.)
    }

    // ---------------- epilogue ----------------
    const long imgC = (long)blockIdx.z * NN;
    #pragma unroll
    for (int mt = 0; mt < 4; ++mt) {
        int r0 = tileM + warpM * 64 + mt * 16 + (lane >> 2);
        #pragma unroll
        for (int nt = 0; nt < 4; ++nt) {
            int c0 = tileN + warpN * 32 + nt * 8 + (lane & 3) * 2;
            if (!STAGE2) {
                uint32_t hp, lp;
                splitpack_h(acc[mt][nt][0], acc[mt][nt][1], hp, lp);
                *reinterpret_cast<uint32_t*>(&OutH[imgC + (long)r0 * N512 + c0]) = hp;
                *reinterpret_cast<uint32_t*>(&OutL[imgC + (long)r0 * N512 + c0]) = lp;
                splitpack_h(acc[mt][nt][2], acc[mt][nt][3], hp, lp);
                *reinterpret_cast<uint32_t*>(&OutH[imgC + (long)(r0 + 8) * N512 + c0]) = hp;
                *reinterpret_cast<uint32_t*>(&OutL[imgC + (long)(r0 + 8) * N512 + c0]) = lp;
            } else {
                *reinterpret_cast<float2*>(&OutF[imgC + (long)r0 * N512 + c0]) =
                    make_float2(acc[mt][nt][0], acc[mt][nt][1]);
                *reinterpret_cast<float2*>(&OutF[imgC + (long)(r0 + 8) * N512 + c0]) =
                    make_float2(acc[mt][nt][2], acc[mt][nt][3]);
            }
        }
    }
}

// ---------------- host launcher ----------------
extern "C" void kernel_launch(void* const* d_in, const int* in_sizes, int n_in,
                              void* d_out, int out_size) {
    const float* X = (const float*)d_in[0];
    float* out = (float*)d_out;

    __half *pXh, *pTmpH, *pTmpL, *pTh, *pTl, *pTth;
    cudaGetSymbolAddress((void**)&pXh,   g_Xh);
    cudaGetSymbolAddress((void**)&pTmpH, g_tmpH);
    cudaGetSymbolAddress((void**)&pTmpL, g_tmpL);
    cudaGetSymbolAddress((void**)&pTh,   g_Th);
    cudaGetSymbolAddress((void**)&pTl,   g_Tl);
    cudaGetSymbolAddress((void**)&pTth,  g_Tth);

    cudaFuncSetAttribute(gemm2p<false>, cudaFuncAttributeMaxDynamicSharedMemorySize, SMEM_TOTAL);
    cudaFuncSetAttribute(gemm2p<true>,  cudaFuncAttributeMaxDynamicSharedMemorySize, SMEM_TOTAL);

    build_basis<<<N512, N512>>>(pTh, pTl, pTth);
    quant_X<<<(int)(NELEM / 4 / 256), 256>>>((const float4*)X, (uint2*)pXh);

    dim3 grid(4, 4, NBATCH);
    // stage 1: C1 = X_h @ (T_h + T_l)   -> hi/lo fp16 intermediate
    gemm2p<false><<<grid, 256, SMEM_TOTAL>>>(pXh, pTh, pTl,
                                             pTmpH, pTmpL, nullptr,
                                             (long)NN, 0L);
    // stage 2: Out = Tt_h @ (C1_h + C1_l) -> fp32 output
    gemm2p<true><<<grid, 256, SMEM_TOTAL>>>(pTth, pTmpH, pTmpL,
                                            nullptr, nullptr, out,
                                            0L, (long)NN);
}

// round 12
// speedup vs baseline: 6.0961x; 1.7029x over previous
#include <cuda_runtime.h>
#include <cuda_fp16.h>
#include <cstdint>

#define N512 512
#define NBATCH 96
#define NN (N512 * N512)
#define NELEM ((size_t)NBATCH * NN)   // 25,165,824

// ---------------- device scratch (no allocations allowed) ----------------
__device__ __half g_Xh[NELEM];          // X quantized fp16
__device__ __half g_tmpH[NELEM];        // stage-1 output (fp16)
__device__ __half g_Th[NN];             // T[k][n]
__device__ __half g_Tth[NN];            // T^T[i][k]

// ---------------- helpers ----------------
__device__ __forceinline__ uint32_t smem_u32(const void* p) {
    uint32_t a;
    asm("{ .reg .u64 t; cvta.to.shared.u64 t, %1; cvt.u32.u64 %0, t; }"
        : "=r"(a) : "l"(p));
    return a;
}

#define LDSM_X4(r0, r1, r2, r3, addr)                                   \
    asm volatile("ldmatrix.sync.aligned.m8n8.x4.shared.b16 "            \
                 "{%0,%1,%2,%3}, [%4];"                                 \
                 : "=r"(r0), "=r"(r1), "=r"(r2), "=r"(r3) : "r"(addr))

#define LDSM_X4T(r0, r1, r2, r3, addr)                                  \
    asm volatile("ldmatrix.sync.aligned.m8n8.x4.trans.shared.b16 "      \
                 "{%0,%1,%2,%3}, [%4];"                                 \
                 : "=r"(r0), "=r"(r1), "=r"(r2), "=r"(r3) : "r"(addr))

#define MMA_F16(c, a, b)                                                \
    asm volatile("mma.sync.aligned.m16n8k16.row.col.f32.f16.f16.f32 "   \
                 "{%0,%1,%2,%3}, {%4,%5,%6,%7}, {%8,%9}, {%0,%1,%2,%3};"\
                 : "+f"((c)[0]), "+f"((c)[1]), "+f"((c)[2]), "+f"((c)[3])\
                 : "r"((a)[0]), "r"((a)[1]), "r"((a)[2]), "r"((a)[3]),  \
                   "r"((b)[0]), "r"((b)[1]))

#define CP_ASYNC16(dst, src)                                            \
    asm volatile("cp.async.cg.shared.global [%0], [%1], 16;"            \
                 :: "r"(dst), "l"(src))
#define CP_COMMIT()  asm volatile("cp.async.commit_group;")
#define CP_WAIT1()   asm volatile("cp.async.wait_group 1;")

// ---------------- prep kernels ----------------
__global__ __launch_bounds__(256)
void quant_X(const float4* __restrict__ X, uint2* __restrict__ H) {
    size_t i = (size_t)blockIdx.x * 256 + threadIdx.x;
    if (i >= NELEM / 4) return;
    float4 v = X[i];
    __half2 p0 = __floats2half2_rn(v.x, v.y);
    __half2 p1 = __floats2half2_rn(v.z, v.w);
    H[i] = make_uint2(*reinterpret_cast<uint32_t*>(&p0),
                      *reinterpret_cast<uint32_t*>(&p1));
}

__global__ void build_basis(__half* __restrict__ Th, __half* __restrict__ Tth) {
    int k = blockIdx.x, n = threadIdx.x;
    float ck = (k == 0) ? rsqrtf(512.0f) : sqrtf(2.0f / 512.0f);
    float v = ck * cospif((float)(k * (2 * n + 1)) * (1.0f / 1024.0f));
    __half h = __float2half_rn(v);
    Th[k * N512 + n]  = h;
    Tth[n * N512 + k] = h;
}

// ---------------- SMEM layout (bytes) ----------------
// BK = 64. A tile: 128 rows x 64 fp16 (128B) pad-> 144B/row = 18432 B
//          B tile:  64 rows x 128 fp16 (256B) pad-> 272B/row = 17408 B
// stage: A | B = 35840 B ; 3 stages = 107520 B  (2 CTAs/SM)
#define A_STRIDE 144
#define B_STRIDE 272
#define A_TILE   18432
#define STAGE_B  35840
#define SMEM_TOTAL (3 * STAGE_B)

// ---------------- GEMM: C = A * B (fp16 in, fp32 acc), single pass --------
// CTA 128x128, BK=64, 8 chunks, 3-stage cp.async, 8 warps, warp tile 64x32.
template <bool STAGE2>
__global__ __launch_bounds__(256, 2)
void gemm1p(const __half* __restrict__ AG,
            const __half* __restrict__ BG,
            __half* __restrict__ OutHalf,
            float* __restrict__ OutF,
            long strideA, long strideB) {
    extern __shared__ __align__(16) char sm[];
    const uint32_t smb = smem_u32(sm);

    const int tid  = threadIdx.x;
    const int lane = tid & 31;
    const int wid  = tid >> 5;
    const int warpM = wid & 1;
    const int warpN = wid >> 1;

    const __half* A = AG + (long)blockIdx.z * strideA;
    const __half* B = BG + (long)blockIdx.z * strideB;

    const int tileM = blockIdx.y * 128;
    const int tileN = blockIdx.x * 128;

    auto issue = [&](int k0, int buf) {
        const uint32_t base = smb + buf * STAGE_B;
        // A: 128 rows x 128B = 1024 x 16B units, 4/thread
        #pragma unroll
        for (int i = 0; i < 4; ++i) {
            int u = tid + i * 256;
            int row = u >> 3;
            int c16 = u & 7;
            uint32_t dst = base + row * A_STRIDE + c16 * 16;
            CP_ASYNC16(dst, &A[(long)(tileM + row) * N512 + k0 + c16 * 8]);
        }
        // B: 64 rows x 256B = 1024 x 16B units, 4/thread
        #pragma unroll
        for (int i = 0; i < 4; ++i) {
            int u = tid + i * 256;
            int row = u >> 4;
            int c16 = u & 15;
            uint32_t dst = base + A_TILE + row * B_STRIDE + c16 * 16;
            CP_ASYNC16(dst, &B[(long)(k0 + row) * N512 + tileN + c16 * 8]);
        }
        CP_COMMIT();
    };

    float acc[4][4][4] = {};

    // ldmatrix lane addressing (bytes, relative to stage base)
    const uint32_t aAddr0 = (uint32_t)((warpM * 64 + (lane & 15)) * A_STRIDE
                                       + (lane >> 4) * 16);
    const uint32_t bAddr0 = (uint32_t)(A_TILE + (lane & 15) * B_STRIDE
                                       + warpN * 64 + (lane >> 4) * 16);

    issue(0, 0);
    issue(64, 1);

    for (int c = 0; c < 8; ++c) {
        const int buf = c % 3;
        CP_WAIT1();
        __syncthreads();
        if (c + 2 < 8) issue((c + 2) * 64, (c + 2) % 3);
        else           CP_COMMIT();          // keep group counting aligned

        const uint32_t sb = smb + buf * STAGE_B;

        #pragma unroll
        for (int ks = 0; ks < 4; ++ks) {
            uint32_t a_[4][4], b_[4][2];
            #pragma unroll
            for (int mt = 0; mt < 4; ++mt) {
                uint32_t ad = sb + aAddr0 + mt * (16 * A_STRIDE) + ks * 32;
                LDSM_X4(a_[mt][0], a_[mt][1], a_[mt][2], a_[mt][3], ad);
            }
            #pragma unroll
            for (int np = 0; np < 2; ++np) {
                uint32_t bd = sb + bAddr0 + ks * (16 * B_STRIDE) + np * 32;
                uint32_t t0, t1, t2, t3;
                LDSM_X4T(t0, t1, t2, t3, bd);
                b_[2 * np][0] = t0;     b_[2 * np][1] = t1;
                b_[2 * np + 1][0] = t2; b_[2 * np + 1][1] = t3;
            }
            #pragma unroll
            for (int mt = 0; mt < 4; ++mt)
                #pragma unroll
                for (int nt = 0; nt < 4; ++nt)
                    MMA_F16(acc[mt][nt], a_[mt], b_[nt]);
        }
    }

    // ---------------- epilogue ----------------
    const long imgC = (long)blockIdx.z * NN;
    #pragma unroll
    for (int mt = 0; mt < 4; ++mt) {
        int r0 = tileM + warpM * 64 + mt * 16 + (lane >> 2);
        #pragma unroll
        for (int nt = 0; nt < 4; ++nt) {
            int c0 = tileN + warpN * 32 + nt * 8 + (lane & 3) * 2;
            if (!STAGE2) {
                __half2 p0 = __floats2half2_rn(acc[mt][nt][0], acc[mt][nt][1]);
                __half2 p1 = __floats2half2_rn(acc[mt][nt][2], acc[mt][nt][3]);
                *reinterpret_cast<__half2*>(&OutHalf[imgC + (long)r0 * N512 + c0]) = p0;
                *reinterpret_cast<__half2*>(&OutHalf[imgC + (long)(r0 + 8) * N512 + c0]) = p1;
            } else {
                *reinterpret_cast<float2*>(&OutF[imgC + (long)r0 * N512 + c0]) =
                    make_float2(acc[mt][nt][0], acc[mt][nt][1]);
                *reinterpret_cast<float2*>(&OutF[imgC + (long)(r0 + 8) * N512 + c0]) =
                    make_float2(acc[mt][nt][2], acc[mt][nt][3]);
            }
        }
    }
}

// ---------------- host launcher ----------------
extern "C" void kernel_launch(void* const* d_in, const int* in_sizes, int n_in,
                              void* d_out, int out_size) {
    const float* X = (const float*)d_in[0];
    float* out = (float*)d_out;

    __half *pXh, *pTmpH, *pTh, *pTth;
    cudaGetSymbolAddress((void**)&pXh,   g_Xh);
    cudaGetSymbolAddress((void**)&pTmpH, g_tmpH);
    cudaGetSymbolAddress((void**)&pTh,   g_Th);
    cudaGetSymbolAddress((void**)&pTth,  g_Tth);

    cudaFuncSetAttribute(gemm1p<false>, cudaFuncAttributeMaxDynamicSharedMemorySize, SMEM_TOTAL);
    cudaFuncSetAttribute(gemm1p<true>,  cudaFuncAttributeMaxDynamicSharedMemorySize, SMEM_TOTAL);

    build_basis<<<N512, N512>>>(pTh, pTth);
    quant_X<<<(int)(NELEM / 4 / 256), 256>>>((const float4*)X, (uint2*)pXh);

    dim3 grid(4, 4, NBATCH);
    // stage 1: C1 = X_h @ T_h   (fp16 intermediate)
    gemm1p<false><<<grid, 256, SMEM_TOTAL>>>(pXh, pTh, pTmpH, nullptr,
                                             (long)NN, 0L);
    // stage 2: Out = Tt_h @ C1  (fp32 output)
    gemm1p<true><<<grid, 256, SMEM_TOTAL>>>(pTth, pTmpH, nullptr, out,
                                            0L, (long)NN);
}